// round 11
// baseline (speedup 1.0000x reference)
#include <cuda_runtime.h>
#include <cstdint>
#include <cfloat>

#define B_ 256
#define F_ 2048
#define C_ 32768
#define P_ 1041
#define NX 32769   // C + 1 (logical row width of x)
#define XP 32772   // padded pitch of g_x rows (multiple of 4 -> 16B-aligned rows)
#define NCHUNK 8   // column chunks for row stats

// ---------------- static device scratch (no allocations allowed) ----------------
static __device__ float g_fn [B_ * F_];   // normalized inputs_feature
static __device__ float g_en [B_ * F_];   // normalized inputs_ema
static __device__ float g_pn [B_ * P_];   // normalized prob
static __device__ float g_pen[B_ * P_];   // normalized prob_ema
static __device__ float g_x  [(size_t)B_ * XP];       // logits / beta (pitched)
static __device__ float g_pm  [B_ * NCHUNK];          // chunk max
static __device__ float g_ps  [B_ * NCHUNK];          // chunk sumexp (rel. chunk max)
static __device__ float g_ptv [B_ * NCHUNK * 7];      // chunk top-7 values
static __device__ int   g_pti [B_ * NCHUNK * 7];      // chunk top-7 indices

// ---------------- K0a: normalize feature/ema rows + l_pos -> x[:,0] ----------------
__global__ __launch_bounds__(256) void k_norm_fe(const float* __restrict__ inf_,
                                                 const float* __restrict__ ine_) {
    int row = blockIdx.x;
    int tid = threadIdx.x;
    const float* fr = inf_ + (size_t)row * F_;
    const float* er = ine_ + (size_t)row * F_;
    float fv[8], ev[8];
    float sf = 0.f, se = 0.f, d = 0.f;
#pragma unroll
    for (int j = 0; j < 8; j++) {
        float a = fr[tid + j * 256];
        float b = er[tid + j * 256];
        fv[j] = a; ev[j] = b;
        sf += a * a; se += b * b; d += a * b;
    }
    __shared__ float s1[256], s2[256], s3[256];
    s1[tid] = sf; s2[tid] = se; s3[tid] = d;
    __syncthreads();
    for (int s = 128; s > 0; s >>= 1) {
        if (tid < s) { s1[tid] += s1[tid + s]; s2[tid] += s2[tid + s]; s3[tid] += s3[tid + s]; }
        __syncthreads();
    }
    float rf = 1.0f / fmaxf(sqrtf(s1[0]), 1e-12f);
    float re = 1.0f / fmaxf(sqrtf(s2[0]), 1e-12f);
#pragma unroll
    for (int j = 0; j < 8; j++) {
        g_fn[(size_t)row * F_ + tid + j * 256] = fv[j] * rf;
        g_en[(size_t)row * F_ + tid + j * 256] = ev[j] * re;
    }
    if (tid == 0) {
        g_x[(size_t)row * XP] = (s3[0] * rf * re) / 0.05f;   // l_pos / beta
    }
}

// ---------------- K0b: normalize prob / prob_ema rows (runs on copy stream) ----------------
__global__ __launch_bounds__(256) void k_norm_p(const float* __restrict__ prob,
                                                const float* __restrict__ probe) {
    int b = blockIdx.x;           // 0..511
    int row = b & 255;
    const float* src = (b < 256) ? prob : probe;
    float* dst = (b < 256) ? g_pn : g_pen;
    int tid = threadIdx.x;
    const float* r = src + (size_t)row * P_;
    float s = 0.f;
    for (int i = tid; i < P_; i += 256) { float v = r[i]; s += v * v; }
    __shared__ float sh[256];
    sh[tid] = s; __syncthreads();
    for (int st = 128; st > 0; st >>= 1) {
        if (tid < st) sh[tid] += sh[tid + st];
        __syncthreads();
    }
    float inv = 1.0f / fmaxf(sqrtf(sh[0]), 1e-12f);
    for (int i = tid; i < P_; i += 256)
        dst[(size_t)row * P_ + i] = r[i] * inv;
}

// ---------------- K1: column scatter into the 4 output queues ----------------
__global__ __launch_bounds__(256) void k_scatter(float* __restrict__ dq,
                                                 float* __restrict__ dq2,
                                                 float* __restrict__ dq3,
                                                 float* __restrict__ dq4,
                                                 const int* __restrict__ tgt) {
    int idx = blockIdx.x * 256 + threadIdx.x;
    const int S0 = F_ * B_;           // 524288
    const int S1 = 2 * S0;            // 1048576
    const int S2 = S1 + P_ * B_;      // 1315072
    const int S3 = S2 + P_ * B_;      // 1581568
    if (idx < S0) {
        int f = idx % F_, i = idx / F_;
        dq[(size_t)f * C_ + tgt[i]] = g_en[idx];               // queue <- ema
    } else if (idx < S1) {
        int j = idx - S0;
        int f = j % F_, i = j / F_;
        dq2[(size_t)f * C_ + tgt[i]] = g_fn[j];                // queue_2 <- f
    } else if (idx < S2) {
        int j = idx - S1;
        int f = j % P_, i = j / P_;
        dq3[(size_t)f * C_ + tgt[i]] = g_pn[j];                // queue_3 <- p
    } else if (idx < S3) {
        int j = idx - S2;
        int f = j % P_, i = j / P_;
        dq4[(size_t)f * C_ + tgt[i]] = g_pen[j];               // queue_4 <- pe
    }
}

// ---------------- K2: fp32 SGEMM via packed fma.rn.f32x2 ----------------
// x[:,1:] = (g_fn @ queue) * 20. 64x128x16 tile, 256 threads, 4x8 microtile
// (4x4 packed f32x2 accumulators). Grid is (row-tiles=4, col-tiles=256):
// the 4 CTAs sharing a queue column tile get CONSECUTIVE bids -> co-resident
// -> 3 of 4 B reads hit L2 (saves ~0.75 GB DRAM vs x-major ordering).
#define BM 64
#define BN 128
#define BK 16

__device__ __forceinline__ unsigned long long splat2(float a) {
    unsigned long long r;
    unsigned int u = __float_as_uint(a);
    asm("mov.b64 %0, {%1, %1};" : "=l"(r) : "r"(u));
    return r;
}

__global__ __launch_bounds__(256, 4) void k_sgemm(const float* __restrict__ Bq) {
    __shared__ float As[BK][BM + 4];
    __shared__ float Bs[BK][BN];
    int bm = blockIdx.x * BM;      // 4 row tiles (fast axis -> consecutive bids)
    int bn = blockIdx.y * BN;      // 256 column tiles
    int tid = threadIdx.x;
    int ty = tid >> 4;           // 0..15 (m: 4 rows each)
    int tx = tid & 15;           // 0..15 (n: 8 cols each)

    unsigned long long acc2[4][4];
#pragma unroll
    for (int i = 0; i < 4; i++)
#pragma unroll
        for (int j = 0; j < 4; j++) acc2[i][j] = 0ull;   // {0.0f, 0.0f}

    const int ar = tid >> 2;            // 0..63 (A row)
    const int ac = (tid & 3) * 4;       // 0,4,8,12 (A col)
    const int br = tid >> 5;            // 0..7 (B row)
    const int bc = (tid & 31) * 4;      // 0..124 (B col)

    const float* Aptr  = &g_fn[(size_t)(bm + ar) * F_ + ac];
    const float* Bptr0 = &Bq[(size_t)br * C_ + bn + bc];
    const float* Bptr1 = &Bq[(size_t)(br + 8) * C_ + bn + bc];
    const size_t bstep = (size_t)BK * C_;

    // prologue: fetch tile 0
    float4 a0 = *(const float4*)(Aptr);
    float4 b0 = *(const float4*)(Bptr0);
    float4 b1 = *(const float4*)(Bptr1);
    Aptr += BK; Bptr0 += bstep; Bptr1 += bstep;

    // no outer unroll: keeps prefetch live-ranges bounded
#pragma unroll 1
    for (int k0 = 0; k0 < F_; k0 += BK) {
        // commit prefetched tile to smem (A transposed to [k][m])
        As[ac + 0][ar] = a0.x; As[ac + 1][ar] = a0.y;
        As[ac + 2][ar] = a0.z; As[ac + 3][ar] = a0.w;
        *(float4*)&Bs[br][bc] = b0;
        *(float4*)&Bs[br + 8][bc] = b1;
        __syncthreads();

        // prefetch next tile while computing current
        if (k0 + BK < F_) {
            a0 = *(const float4*)(Aptr);
            b0 = *(const float4*)(Bptr0);
            b1 = *(const float4*)(Bptr1);
            Aptr += BK; Bptr0 += bstep; Bptr1 += bstep;
        }

#pragma unroll
        for (int kk = 0; kk < BK; kk++) {
            float4 av = *(const float4*)&As[kk][ty * 4];
            ulonglong2 bq0 = *(const ulonglong2*)&Bs[kk][tx * 8];
            ulonglong2 bq1 = *(const ulonglong2*)&Bs[kk][tx * 8 + 4];
            unsigned long long bp[4] = {bq0.x, bq0.y, bq1.x, bq1.y};
            unsigned long long ap[4];
            ap[0] = splat2(av.x); ap[1] = splat2(av.y);
            ap[2] = splat2(av.z); ap[3] = splat2(av.w);
#pragma unroll
            for (int i = 0; i < 4; i++)
#pragma unroll
                for (int j = 0; j < 4; j++)
                    asm("fma.rn.f32x2 %0, %1, %2, %0;"
                        : "+l"(acc2[i][j]) : "l"(ap[i]), "l"(bp[j]));
        }
        __syncthreads();
    }

    // epilogue: unpack, scale by 20 = 1/0.05, scalar stores (col offset +1 unaligned)
#pragma unroll
    for (int i = 0; i < 4; i++) {
        int row = bm + ty * 4 + i;
        float* xr = g_x + (size_t)row * XP + 1 + bn + tx * 8;
#pragma unroll
        for (int j = 0; j < 4; j++) {
            unsigned int lo, hi;
            asm("mov.b64 {%0, %1}, %2;" : "=r"(lo), "=r"(hi) : "l"(acc2[i][j]));
            xr[j * 2 + 0] = __uint_as_float(lo) * 20.0f;
            xr[j * 2 + 1] = __uint_as_float(hi) * 20.0f;
        }
    }
}

// ---------------- K3: per-(row,chunk) max, sumexp, top-7 (jax tie-break) ----------------
// Chunks are ALIGNED: chunk c covers [c*4096, (c+1)*4096); chunk 7 additionally
// takes element 32768. The partition is arbitrary (merge is index-exact), so
// this keeps every load a 16B-aligned LDG.128.
__device__ __forceinline__ bool better(float v, int i, float u, int k) {
    return (v > u) || (v == u && i < k);
}

__global__ __launch_bounds__(256) void k_partial() {
    int row = blockIdx.x >> 3;          // 0..255
    int chunk = blockIdx.x & 7;         // 0..7
    int tid = threadIdx.x;
    const float* xr = g_x + (size_t)row * XP;
    int start = chunk * 4096;

    float lv[7]; int li[7];
#pragma unroll
    for (int j = 0; j < 7; j++) { lv[j] = -FLT_MAX; li[j] = 0x7fffffff; }

    float vals[16];                      // statically indexed -> registers
#pragma unroll
    for (int j = 0; j < 4; j++) {
        int i0 = start + (tid + j * 256) * 4;
        float4 vv = *(const float4*)&xr[i0];
        vals[j * 4 + 0] = vv.x; vals[j * 4 + 1] = vv.y;
        vals[j * 4 + 2] = vv.z; vals[j * 4 + 3] = vv.w;
#pragma unroll
        for (int q = 0; q < 4; q++) {
            float v = vals[j * 4 + q];
            int i = i0 + q;
            if (better(v, i, lv[6], li[6])) {
                lv[6] = v; li[6] = i;
#pragma unroll
                for (int p = 6; p > 0; p--) {
                    if (better(lv[p], li[p], lv[p - 1], li[p - 1])) {
                        float tv = lv[p]; lv[p] = lv[p - 1]; lv[p - 1] = tv;
                        int ti = li[p]; li[p] = li[p - 1]; li[p - 1] = ti;
                    }
                }
            }
        }
    }

    // tail element 32768 handled by (chunk 7, tid 0)
    float extra = -FLT_MAX;
    if (chunk == 7 && tid == 0) {
        extra = xr[32768];
        if (better(extra, 32768, lv[6], li[6])) {
            lv[6] = extra; li[6] = 32768;
#pragma unroll
            for (int p = 6; p > 0; p--) {
                if (better(lv[p], li[p], lv[p - 1], li[p - 1])) {
                    float tv = lv[p]; lv[p] = lv[p - 1]; lv[p - 1] = tv;
                    int ti = li[p]; li[p] = li[p - 1]; li[p - 1] = ti;
                }
            }
        }
    }

    // block max
    __shared__ float sred[256];
    __shared__ int   sredi[256];
    sred[tid] = lv[0]; __syncthreads();
    for (int s = 128; s > 0; s >>= 1) {
        if (tid < s) sred[tid] = fmaxf(sred[tid], sred[tid + s]);
        __syncthreads();
    }
    float cmax = sred[0];
    __syncthreads();

    // sumexp relative to chunk max. __expf = bare MUFU ex2 path (8.4M exps
    // chip-wide: this kernel is MUFU-bound). -FLT_MAX extra underflows to 0.
    float sum = 0.f;
#pragma unroll
    for (int j = 0; j < 16; j++) sum += __expf(vals[j] - cmax);
    sum += __expf(extra - cmax);
    sred[tid] = sum; __syncthreads();
    for (int s = 128; s > 0; s >>= 1) {
        if (tid < s) sred[tid] += sred[tid + s];
        __syncthreads();
    }
    if (tid == 0) {
        g_pm[row * NCHUNK + chunk] = cmax;
        g_ps[row * NCHUNK + chunk] = sred[0];
    }
    __syncthreads();

    // block top-7: 7 argmax rounds over 256x7 candidates in shared
    __shared__ float sv[7 * 256];
    __shared__ int   si[7 * 256];
#pragma unroll
    for (int j = 0; j < 7; j++) { sv[tid * 7 + j] = lv[j]; si[tid * 7 + j] = li[j]; }
    __syncthreads();
    for (int sel = 0; sel < 7; sel++) {
        float bv = -FLT_MAX; int bi = 0x7fffffff;
#pragma unroll
        for (int j = 0; j < 7; j++) {
            float v = sv[tid * 7 + j]; int i = si[tid * 7 + j];
            if (better(v, i, bv, bi)) { bv = v; bi = i; }
        }
        sred[tid] = bv; sredi[tid] = bi; __syncthreads();
        for (int s = 128; s > 0; s >>= 1) {
            if (tid < s) {
                if (better(sred[tid + s], sredi[tid + s], sred[tid], sredi[tid])) {
                    sred[tid] = sred[tid + s]; sredi[tid] = sredi[tid + s];
                }
            }
            __syncthreads();
        }
        float wv = sred[0]; int wi = sredi[0];
        __syncthreads();
        if (tid == 0) {
            g_ptv[(row * NCHUNK + chunk) * 7 + sel] = wv;
            g_pti[(row * NCHUNK + chunk) * 7 + sel] = wi;
        }
#pragma unroll
        for (int j = 0; j < 7; j++) {
            if (si[tid * 7 + j] == wi) { sv[tid * 7 + j] = -FLT_MAX; si[tid * 7 + j] = 0x7fffffff; }
        }
        __syncthreads();
    }
}

// ---------------- K4: merge partials, oh scatter, loss ----------------
__global__ __launch_bounds__(256) void k_merge_finalize(const int* __restrict__ targets,
                                                        float* __restrict__ out,
                                                        float* __restrict__ oh_base) {
    int row = threadIdx.x;  // 256 rows, 1 block

    // combine lse
    float M = -FLT_MAX;
#pragma unroll
    for (int c = 0; c < NCHUNK; c++) M = fmaxf(M, g_pm[row * NCHUNK + c]);
    float S = 0.f;
#pragma unroll
    for (int c = 0; c < NCHUNK; c++)
        S += g_ps[row * NCHUNK + c] * expf(g_pm[row * NCHUNK + c] - M);
    float lse = M + logf(S);

    // merge 8x7 candidates into global top-7
    float v[7]; int id[7];
#pragma unroll
    for (int j = 0; j < 7; j++) { v[j] = -FLT_MAX; id[j] = 0x7fffffff; }
#pragma unroll
    for (int c = 0; c < NCHUNK; c++) {
#pragma unroll
        for (int q = 0; q < 7; q++) {
            float cv = g_ptv[(row * NCHUNK + c) * 7 + q];
            int   ci = g_pti[(row * NCHUNK + c) * 7 + q];
            if (better(cv, ci, v[6], id[6])) {
                v[6] = cv; id[6] = ci;
#pragma unroll
                for (int j = 6; j > 0; j--) {
                    if (better(v[j], id[j], v[j - 1], id[j - 1])) {
                        float tv = v[j]; v[j] = v[j - 1]; v[j - 1] = tv;
                        int ti = id[j]; id[j] = id[j - 1]; id[j - 1] = ti;
                    }
                }
            }
        }
    }

    int t = targets[row];               // NOTE: raw target used as oh column (ref quirk)
    float xt = g_x[(size_t)row * XP + t];

    // softmax over ranks 1..6
    float mx = v[1];
    float es[6], ss = 0.f;
#pragma unroll
    for (int j = 1; j < 7; j++) { es[j - 1] = expf(v[j] - mx); ss += es[j - 1]; }
    float inv = 1.0f / ss;

    float loss = lse - xt;               // target weight 1.0
    float* oh = oh_base + (size_t)row * NX;
#pragma unroll
    for (int j = 1; j < 7; j++) {
        float w = es[j - 1] * inv;
        if (id[j] != t) {
            oh[id[j]] = w;
            loss += w * (lse - v[j]);
        }
    }
    oh[t] = 1.0f;

    __shared__ float sh[256];
    sh[row] = loss; __syncthreads();
    for (int s = 128; s > 0; s >>= 1) {
        if (row < s) sh[row] += sh[row + s];
        __syncthreads();
    }
    if (row == 0) out[0] = sh[0] * (1.0f / 256.0f);
}

// ---------------- launch ----------------
extern "C" void kernel_launch(void* const* d_in, const int* in_sizes, int n_in,
                              void* d_out, int out_size) {
    (void)in_sizes; (void)n_in; (void)out_size;
    const float* inf_  = (const float*)d_in[0];
    const float* ine_  = (const float*)d_in[1];
    const float* prob  = (const float*)d_in[2];
    const float* probe = (const float*)d_in[3];
    const float* queue = (const float*)d_in[4];
    const float* q2in  = (const float*)d_in[5];
    const float* q3in  = (const float*)d_in[6];
    const float* q4in  = (const float*)d_in[7];
    const int*   tgt   = (const int*)d_in[8];
    float* out = (float*)d_out;

    const size_t SZ_Q  = (size_t)F_ * C_;   // 67108864
    const size_t SZ_Q3 = (size_t)P_ * C_;   // 34111488
    float* oq  = out + 1;
    float* oq2 = oq  + SZ_Q;
    float* oq3 = oq2 + SZ_Q;
    float* oq4 = oq3 + SZ_Q3;
    float* ooh = oq4 + SZ_Q3;

    // Try to fork a side stream for copies + prob-normalize + scatter.
    // If ANY creation fails, fall back to a fully sequential schedule.
    cudaStream_t s1 = 0;
    cudaEvent_t evA = 0, evB = 0, evC = 0;
    bool fork = true;
    if (cudaStreamCreateWithFlags(&s1, cudaStreamNonBlocking) != cudaSuccess) fork = false;
    if (fork && cudaEventCreateWithFlags(&evA, cudaEventDisableTiming) != cudaSuccess) fork = false;
    if (fork && cudaEventCreateWithFlags(&evB, cudaEventDisableTiming) != cudaSuccess) fork = false;
    if (fork && cudaEventCreateWithFlags(&evC, cudaEventDisableTiming) != cudaSuccess) fork = false;

    if (fork) {
        cudaEventRecord(evA, 0);
        cudaStreamWaitEvent(s1, evA, 0);

        // s1: bulk queue copies (pre-update values), independent of compute (CE path)
        cudaMemcpyAsync(oq,  queue, SZ_Q  * sizeof(float), cudaMemcpyDeviceToDevice, s1);
        cudaMemcpyAsync(oq2, q2in,  SZ_Q  * sizeof(float), cudaMemcpyDeviceToDevice, s1);
        cudaMemcpyAsync(oq3, q3in,  SZ_Q3 * sizeof(float), cudaMemcpyDeviceToDevice, s1);
        cudaMemcpyAsync(oq4, q4in,  SZ_Q3 * sizeof(float), cudaMemcpyDeviceToDevice, s1);

        // s0: normalize f/ema only (the sgemm dependency)
        k_norm_fe<<<B_, 256>>>(inf_, ine_);
        cudaEventRecord(evB, 0);             // g_fn/g_en ready -> s1 may scatter

        // s0: logits/beta (reads original queue; independent of output copies)
        {
            dim3 grid(B_ / BM, C_ / BN);  // (4, 256): row-tiles fast for L2 reuse
            k_sgemm<<<grid, 256>>>(queue);
        }

        // s1: prob normalize (feeds only scatter), then scatter + zero oh region
        k_norm_p<<<2 * B_, 256, 0, s1>>>(prob, probe);
        cudaStreamWaitEvent(s1, evB, 0);
        {
            int total = 2 * F_ * B_ + 2 * P_ * B_;   // 1581568
            k_scatter<<<(total + 255) / 256, 256, 0, s1>>>(oq, oq2, oq3, oq4, tgt);
        }
        cudaMemsetAsync(ooh, 0, (size_t)B_ * NX * sizeof(float), s1);
        cudaEventRecord(evC, s1);

        // s0: row stats (depends on sgemm)
        k_partial<<<B_ * NCHUNK, 256>>>();

        // join s1 back before finalize
        cudaStreamWaitEvent(0, evC, 0);
        k_merge_finalize<<<1, 256>>>(tgt, out, ooh);

        // Query capture status on the CREATED stream (querying the legacy
        // stream during an active capture returns cudaErrorStreamCaptureImplicit).
        // Destroy only when not capturing; leak once on the capture call.
        cudaStreamCaptureStatus st = cudaStreamCaptureStatusNone;
        cudaError_t qe = cudaStreamIsCapturing(s1, &st);
        if (qe == cudaSuccess && st == cudaStreamCaptureStatusNone) {
            cudaEventDestroy(evA);
            cudaEventDestroy(evB);
            cudaEventDestroy(evC);
            cudaStreamDestroy(s1);
        }
    } else {
        // -------- sequential fallback: everything on stream 0 --------
        k_norm_fe<<<B_, 256>>>(inf_, ine_);
        k_norm_p<<<2 * B_, 256>>>(prob, probe);
        {
            dim3 grid(B_ / BM, C_ / BN);
            k_sgemm<<<grid, 256>>>(queue);
        }
        cudaMemcpyAsync(oq,  queue, SZ_Q  * sizeof(float), cudaMemcpyDeviceToDevice, 0);
        cudaMemcpyAsync(oq2, q2in,  SZ_Q  * sizeof(float), cudaMemcpyDeviceToDevice, 0);
        cudaMemcpyAsync(oq3, q3in,  SZ_Q3 * sizeof(float), cudaMemcpyDeviceToDevice, 0);
        cudaMemcpyAsync(oq4, q4in,  SZ_Q3 * sizeof(float), cudaMemcpyDeviceToDevice, 0);
        {
            int total = 2 * F_ * B_ + 2 * P_ * B_;
            k_scatter<<<(total + 255) / 256, 256>>>(oq, oq2, oq3, oq4, tgt);
        }
        cudaMemsetAsync(ooh, 0, (size_t)B_ * NX * sizeof(float), 0);
        k_partial<<<B_ * NCHUNK, 256>>>();
        k_merge_finalize<<<1, 256>>>(tgt, out, ooh);
    }
}

// round 15
// speedup vs baseline: 1.7956x; 1.7956x over previous
#include <cuda_runtime.h>
#include <cuda_bf16.h>
#include <cstdint>
#include <cfloat>

#define B_ 256
#define F_ 2048
#define C_ 32768
#define P_ 1041
#define NX 32769   // C + 1 (logical row width of x)
#define XP 32772   // padded pitch of g_x rows (multiple of 4 -> 16B-aligned rows)
#define NCHUNK 8   // column chunks for row stats
#define KP (F_/2)  // 1024 packed k-pairs

// ---------------- static device scratch (no allocations allowed) ----------------
static __device__ float g_fn [B_ * F_];   // normalized inputs_feature
static __device__ float g_en [B_ * F_];   // normalized inputs_ema
static __device__ float g_pn [B_ * P_];   // normalized prob
static __device__ float g_pen[B_ * P_];   // normalized prob_ema
static __device__ float g_x  [(size_t)B_ * XP];       // logits / beta (pitched)
static __device__ float g_pm  [B_ * NCHUNK];
static __device__ float g_ps  [B_ * NCHUNK];
static __device__ float g_ptv [B_ * NCHUNK * 7];
static __device__ int   g_pti [B_ * NCHUNK * 7];
// bf16-split A operand, k-pair packed: word = (bf16(k_even) | bf16(k_odd)<<16)
static __device__ unsigned int g_aph[B_ * KP];           // fn hi     [m][kp]
static __device__ unsigned int g_apl[B_ * KP];           // fn lo     [m][kp]

// ---------------- K0a: normalize feature/ema rows + l_pos -> x[:,0] ----------------
__global__ __launch_bounds__(256) void k_norm_fe(const float* __restrict__ inf_,
                                                 const float* __restrict__ ine_) {
    int row = blockIdx.x;
    int tid = threadIdx.x;
    const float* fr = inf_ + (size_t)row * F_;
    const float* er = ine_ + (size_t)row * F_;
    float fv[8], ev[8];
    float sf = 0.f, se = 0.f, d = 0.f;
#pragma unroll
    for (int j = 0; j < 8; j++) {
        float a = fr[tid + j * 256];
        float b = er[tid + j * 256];
        fv[j] = a; ev[j] = b;
        sf += a * a; se += b * b; d += a * b;
    }
    __shared__ float s1[256], s2[256], s3[256];
    s1[tid] = sf; s2[tid] = se; s3[tid] = d;
    __syncthreads();
    for (int s = 128; s > 0; s >>= 1) {
        if (tid < s) { s1[tid] += s1[tid + s]; s2[tid] += s2[tid + s]; s3[tid] += s3[tid + s]; }
        __syncthreads();
    }
    float rf = 1.0f / fmaxf(sqrtf(s1[0]), 1e-12f);
    float re = 1.0f / fmaxf(sqrtf(s2[0]), 1e-12f);
#pragma unroll
    for (int j = 0; j < 8; j++) {
        g_fn[(size_t)row * F_ + tid + j * 256] = fv[j] * rf;
        g_en[(size_t)row * F_ + tid + j * 256] = ev[j] * re;
    }
    if (tid == 0) {
        g_x[(size_t)row * XP] = (s3[0] * rf * re) / 0.05f;   // l_pos / beta
    }
}

// ---------------- K0b: normalize prob / prob_ema rows (copy stream) ----------------
__global__ __launch_bounds__(256) void k_norm_p(const float* __restrict__ prob,
                                                const float* __restrict__ probe) {
    int b = blockIdx.x;           // 0..511
    int row = b & 255;
    const float* src = (b < 256) ? prob : probe;
    float* dst = (b < 256) ? g_pn : g_pen;
    int tid = threadIdx.x;
    const float* r = src + (size_t)row * P_;
    float s = 0.f;
    for (int i = tid; i < P_; i += 256) { float v = r[i]; s += v * v; }
    __shared__ float sh[256];
    sh[tid] = s; __syncthreads();
    for (int st = 128; st > 0; st >>= 1) {
        if (tid < st) sh[tid] += sh[tid + st];
        __syncthreads();
    }
    float inv = 1.0f / fmaxf(sqrtf(sh[0]), 1e-12f);
    for (int i = tid; i < P_; i += 256)
        dst[(size_t)row * P_ + i] = r[i] * inv;
}

// ---------------- split helper ----------------
__device__ __forceinline__ void split_pack(float x0, float x1,
                                           unsigned int& h, unsigned int& l) {
    __nv_bfloat16 h0 = __float2bfloat16_rn(x0);
    __nv_bfloat16 h1 = __float2bfloat16_rn(x1);
    __nv_bfloat16 l0 = __float2bfloat16_rn(x0 - __bfloat162float(h0));
    __nv_bfloat16 l1 = __float2bfloat16_rn(x1 - __bfloat162float(h1));
    h = (unsigned int)__bfloat16_as_ushort(h0) | ((unsigned int)__bfloat16_as_ushort(h1) << 16);
    l = (unsigned int)__bfloat16_as_ushort(l0) | ((unsigned int)__bfloat16_as_ushort(l1) << 16);
}

// g_fn [B][F] fp32 -> k-pair-packed hi/lo [B][KP]
__global__ __launch_bounds__(256) void k_split_a() {
    int idx = blockIdx.x * 256 + threadIdx.x;   // < B_*KP
    int m = idx / KP, kp = idx % KP;
    float x0 = g_fn[(size_t)m * F_ + 2 * kp];
    float x1 = g_fn[(size_t)m * F_ + 2 * kp + 1];
    unsigned int h, l;
    split_pack(x0, x1, h, l);
    g_aph[idx] = h;
    g_apl[idx] = l;
}

// ---------------- K1: column scatter into the 4 output queues ----------------
__global__ __launch_bounds__(256) void k_scatter(float* __restrict__ dq,
                                                 float* __restrict__ dq2,
                                                 float* __restrict__ dq3,
                                                 float* __restrict__ dq4,
                                                 const int* __restrict__ tgt) {
    int idx = blockIdx.x * 256 + threadIdx.x;
    const int S0 = F_ * B_;
    const int S1 = 2 * S0;
    const int S2 = S1 + P_ * B_;
    const int S3 = S2 + P_ * B_;
    if (idx < S0) {
        int f = idx % F_, i = idx / F_;
        dq[(size_t)f * C_ + tgt[i]] = g_en[idx];
    } else if (idx < S1) {
        int j = idx - S0;
        int f = j % F_, i = j / F_;
        dq2[(size_t)f * C_ + tgt[i]] = g_fn[j];
    } else if (idx < S2) {
        int j = idx - S1;
        int f = j % P_, i = j / P_;
        dq3[(size_t)f * C_ + tgt[i]] = g_pn[j];
    } else if (idx < S3) {
        int j = idx - S2;
        int f = j % P_, i = j / P_;
        dq4[(size_t)f * C_ + tgt[i]] = g_pen[j];
    }
}

// ---------------- K2: bf16-split tensor-core GEMM (mma.sync m16n8k16) ----------------
// x[:,1:] = (fn @ queue) * 20 computed as Ah*Bh + Ah*Bl + Al*Bh in fp32 accum.
// B is loaded DIRECTLY from the fp32 queue and split/packed in registers
// (fp32 bytes == hi+lo bf16 bytes: identical traffic, no separate split pass).
// CTA tile 64(m) x 128(n); 8 warps as 2x4; 64 chunks of 16 k-pairs (32 k),
// register-prefetched double buffering of the global loads.
#define GBM 64
#define GBN 128
#define SAP 20    // sA row stride (uint32): banks gid*20+tig -> all 32 distinct
#define SBP 136   // sB row stride (uint32): banks tig*8+gid -> all 32 distinct

__device__ __forceinline__ void mma_bf16(float& d0, float& d1, float& d2, float& d3,
                                         unsigned int a0, unsigned int a1,
                                         unsigned int a2, unsigned int a3,
                                         unsigned int b0, unsigned int b1) {
    asm("mma.sync.aligned.m16n8k16.row.col.f32.bf16.bf16.f32 "
        "{%0,%1,%2,%3}, {%4,%5,%6,%7}, {%8,%9}, {%0,%1,%2,%3};"
        : "+f"(d0), "+f"(d1), "+f"(d2), "+f"(d3)
        : "r"(a0), "r"(a1), "r"(a2), "r"(a3), "r"(b0), "r"(b1));
}

__device__ __forceinline__ void pack4(const float4& e, const float4& o,
                                      uint4& h, uint4& l) {
    split_pack(e.x, o.x, h.x, l.x);
    split_pack(e.y, o.y, h.y, l.y);
    split_pack(e.z, o.z, h.z, l.z);
    split_pack(e.w, o.w, h.w, l.w);
}

__global__ __launch_bounds__(256, 2) void k_gemm_bf16(const float* __restrict__ Bq) {
    __shared__ unsigned int sAh[GBM * SAP], sAl[GBM * SAP];     // [m][kp] (16 kp used)
    __shared__ unsigned int sBh[16 * SBP], sBl[16 * SBP];       // [kp][n] (128 n used)

    int bm = blockIdx.x * GBM;     // 4 row tiles (fast axis -> consecutive bids, L2 reuse)
    int bn = blockIdx.y * GBN;     // 256 col tiles
    int tid = threadIdx.x;
    int lane = tid & 31, warp = tid >> 5;
    int gid = lane >> 2, tig = lane & 3;
    int wm = warp & 1, wn = warp >> 1;       // 2 x 4 warp grid

    float d[2][4][4];
#pragma unroll
    for (int mt = 0; mt < 2; mt++)
#pragma unroll
        for (int nt = 0; nt < 4; nt++)
#pragma unroll
            for (int r = 0; r < 4; r++) d[mt][nt][r] = 0.f;

    // per-chunk assignments:
    //  B packed tile: 16 kp rows x 32 uint4 cols = 512 uint4; thread does 2
    //    (rows brow0, brow0+8), each packed uint4 <- fp32 float4 pair (even/odd k row).
    //  A packed tile: 64 rows x 4 uint4 = 256; thread does 1.
    int brow0 = tid >> 5;            // 0..7
    int brow1 = brow0 + 8;           // 8..15
    int bc = tid & 31;
    int arow = tid >> 2, ac4 = tid & 3;

    const float4* pE0 = (const float4*)&Bq[(size_t)(2 * brow0) * C_ + bn] + bc;
    const float4* pE1 = (const float4*)&Bq[(size_t)(2 * brow1) * C_ + bn] + bc;
    const size_t crow = C_ / 4;                 // one fp32 k row in float4 units
    const size_t bstep = (size_t)32 * crow;     // 32 k rows per chunk
    const uint4* pAH  = (const uint4*)&g_aph[(size_t)(bm + arow) * KP] + ac4;
    const uint4* pAL  = (const uint4*)&g_apl[(size_t)(bm + arow) * KP] + ac4;
    const size_t astep = 16 / 4;

    // prologue: fetch chunk 0 into registers
    float4 rE0 = *pE0, rO0 = *(pE0 + crow);
    float4 rE1 = *pE1, rO1 = *(pE1 + crow);
    uint4 rAH = *pAH, rAL = *pAL;
    pE0 += bstep; pE1 += bstep;
    pAH += astep; pAL += astep;

#pragma unroll 1
    for (int kc = 0; kc < KP / 16; kc++) {
        // split/pack prefetched fp32 B into hi/lo and commit to smem
        {
            uint4 h0, l0, h1, l1;
            pack4(rE0, rO0, h0, l0);
            pack4(rE1, rO1, h1, l1);
            *(uint4*)&sBh[brow0 * SBP + bc * 4] = h0;
            *(uint4*)&sBl[brow0 * SBP + bc * 4] = l0;
            *(uint4*)&sBh[brow1 * SBP + bc * 4] = h1;
            *(uint4*)&sBl[brow1 * SBP + bc * 4] = l1;
        }
        *(uint4*)&sAh[arow * SAP + ac4 * 4] = rAH;
        *(uint4*)&sAl[arow * SAP + ac4 * 4] = rAL;
        __syncthreads();

        // prefetch next chunk during compute
        if (kc + 1 < KP / 16) {
            rE0 = *pE0; rO0 = *(pE0 + crow);
            rE1 = *pE1; rO1 = *(pE1 + crow);
            rAH = *pAH; rAL = *pAL;
            pE0 += bstep; pE1 += bstep;
            pAH += astep; pAL += astep;
        }

#pragma unroll
        for (int s = 0; s < 2; s++) {        // two k16 steps per chunk
            int kb = s * 8;                  // k-pair base within chunk
            unsigned int afh[2][4], afl[2][4];
#pragma unroll
            for (int mt = 0; mt < 2; mt++) {
                int row = wm * 32 + mt * 16 + gid;
                afh[mt][0] = sAh[row * SAP + kb + tig];
                afh[mt][1] = sAh[(row + 8) * SAP + kb + tig];
                afh[mt][2] = sAh[row * SAP + kb + tig + 4];
                afh[mt][3] = sAh[(row + 8) * SAP + kb + tig + 4];
                afl[mt][0] = sAl[row * SAP + kb + tig];
                afl[mt][1] = sAl[(row + 8) * SAP + kb + tig];
                afl[mt][2] = sAl[row * SAP + kb + tig + 4];
                afl[mt][3] = sAl[(row + 8) * SAP + kb + tig + 4];
            }
            unsigned int bfh[4][2], bfl[4][2];
#pragma unroll
            for (int nt = 0; nt < 4; nt++) {
                int col = wn * 32 + nt * 8 + gid;
                bfh[nt][0] = sBh[(kb + tig) * SBP + col];
                bfh[nt][1] = sBh[(kb + tig + 4) * SBP + col];
                bfl[nt][0] = sBl[(kb + tig) * SBP + col];
                bfl[nt][1] = sBl[(kb + tig + 4) * SBP + col];
            }
#pragma unroll
            for (int mt = 0; mt < 2; mt++)
#pragma unroll
                for (int nt = 0; nt < 4; nt++) {
                    mma_bf16(d[mt][nt][0], d[mt][nt][1], d[mt][nt][2], d[mt][nt][3],
                             afh[mt][0], afh[mt][1], afh[mt][2], afh[mt][3],
                             bfh[nt][0], bfh[nt][1]);
                    mma_bf16(d[mt][nt][0], d[mt][nt][1], d[mt][nt][2], d[mt][nt][3],
                             afh[mt][0], afh[mt][1], afh[mt][2], afh[mt][3],
                             bfl[nt][0], bfl[nt][1]);
                    mma_bf16(d[mt][nt][0], d[mt][nt][1], d[mt][nt][2], d[mt][nt][3],
                             afl[mt][0], afl[mt][1], afl[mt][2], afl[mt][3],
                             bfh[nt][0], bfh[nt][1]);
                }
        }
        __syncthreads();
    }

    // epilogue: scale by 20 = 1/0.05, scatter to pitched g_x (+1 col offset)
#pragma unroll
    for (int mt = 0; mt < 2; mt++) {
        int row = bm + wm * 32 + mt * 16 + gid;
#pragma unroll
        for (int nt = 0; nt < 4; nt++) {
            int col = 1 + bn + wn * 32 + nt * 8 + 2 * tig;
            g_x[(size_t)row * XP + col]           = d[mt][nt][0] * 20.0f;
            g_x[(size_t)row * XP + col + 1]       = d[mt][nt][1] * 20.0f;
            g_x[(size_t)(row + 8) * XP + col]     = d[mt][nt][2] * 20.0f;
            g_x[(size_t)(row + 8) * XP + col + 1] = d[mt][nt][3] * 20.0f;
        }
    }
}

// ---------------- K3: per-(row,chunk) max, sumexp, top-7 (jax tie-break) ----------------
__device__ __forceinline__ bool better(float v, int i, float u, int k) {
    return (v > u) || (v == u && i < k);
}

__global__ __launch_bounds__(256) void k_partial() {
    int row = blockIdx.x >> 3;
    int chunk = blockIdx.x & 7;
    int tid = threadIdx.x;
    const float* xr = g_x + (size_t)row * XP;
    int start = chunk * 4096;

    float lv[7]; int li[7];
#pragma unroll
    for (int j = 0; j < 7; j++) { lv[j] = -FLT_MAX; li[j] = 0x7fffffff; }

    float vals[16];
#pragma unroll
    for (int j = 0; j < 4; j++) {
        int i0 = start + (tid + j * 256) * 4;
        float4 vv = *(const float4*)&xr[i0];
        vals[j * 4 + 0] = vv.x; vals[j * 4 + 1] = vv.y;
        vals[j * 4 + 2] = vv.z; vals[j * 4 + 3] = vv.w;
#pragma unroll
        for (int q = 0; q < 4; q++) {
            float v = vals[j * 4 + q];
            int i = i0 + q;
            if (better(v, i, lv[6], li[6])) {
                lv[6] = v; li[6] = i;
#pragma unroll
                for (int p = 6; p > 0; p--) {
                    if (better(lv[p], li[p], lv[p - 1], li[p - 1])) {
                        float tv = lv[p]; lv[p] = lv[p - 1]; lv[p - 1] = tv;
                        int ti = li[p]; li[p] = li[p - 1]; li[p - 1] = ti;
                    }
                }
            }
        }
    }

    float extra = -FLT_MAX;
    if (chunk == 7 && tid == 0) {
        extra = xr[32768];
        if (better(extra, 32768, lv[6], li[6])) {
            lv[6] = extra; li[6] = 32768;
#pragma unroll
            for (int p = 6; p > 0; p--) {
                if (better(lv[p], li[p], lv[p - 1], li[p - 1])) {
                    float tv = lv[p]; lv[p] = lv[p - 1]; lv[p - 1] = tv;
                    int ti = li[p]; li[p] = li[p - 1]; li[p - 1] = ti;
                }
            }
        }
    }

    __shared__ float sred[256];
    __shared__ int   sredi[256];
    sred[tid] = lv[0]; __syncthreads();
    for (int s = 128; s > 0; s >>= 1) {
        if (tid < s) sred[tid] = fmaxf(sred[tid], sred[tid + s]);
        __syncthreads();
    }
    float cmax = sred[0];
    __syncthreads();

    float sum = 0.f;
#pragma unroll
    for (int j = 0; j < 16; j++) sum += __expf(vals[j] - cmax);
    sum += __expf(extra - cmax);
    sred[tid] = sum; __syncthreads();
    for (int s = 128; s > 0; s >>= 1) {
        if (tid < s) sred[tid] += sred[tid + s];
        __syncthreads();
    }
    if (tid == 0) {
        g_pm[row * NCHUNK + chunk] = cmax;
        g_ps[row * NCHUNK + chunk] = sred[0];
    }
    __syncthreads();

    __shared__ float sv[7 * 256];
    __shared__ int   si[7 * 256];
#pragma unroll
    for (int j = 0; j < 7; j++) { sv[tid * 7 + j] = lv[j]; si[tid * 7 + j] = li[j]; }
    __syncthreads();
    for (int sel = 0; sel < 7; sel++) {
        float bv = -FLT_MAX; int bi = 0x7fffffff;
#pragma unroll
        for (int j = 0; j < 7; j++) {
            float v = sv[tid * 7 + j]; int i = si[tid * 7 + j];
            if (better(v, i, bv, bi)) { bv = v; bi = i; }
        }
        sred[tid] = bv; sredi[tid] = bi; __syncthreads();
        for (int s = 128; s > 0; s >>= 1) {
            if (tid < s) {
                if (better(sred[tid + s], sredi[tid + s], sred[tid], sredi[tid])) {
                    sred[tid] = sred[tid + s]; sredi[tid] = sredi[tid + s];
                }
            }
            __syncthreads();
        }
        float wv = sred[0]; int wi = sredi[0];
        __syncthreads();
        if (tid == 0) {
            g_ptv[(row * NCHUNK + chunk) * 7 + sel] = wv;
            g_pti[(row * NCHUNK + chunk) * 7 + sel] = wi;
        }
#pragma unroll
        for (int j = 0; j < 7; j++) {
            if (si[tid * 7 + j] == wi) { sv[tid * 7 + j] = -FLT_MAX; si[tid * 7 + j] = 0x7fffffff; }
        }
        __syncthreads();
    }
}

// ---------------- K4: merge partials, oh scatter, loss ----------------
__global__ __launch_bounds__(256) void k_merge_finalize(const int* __restrict__ targets,
                                                        float* __restrict__ out,
                                                        float* __restrict__ oh_base) {
    int row = threadIdx.x;

    float M = -FLT_MAX;
#pragma unroll
    for (int c = 0; c < NCHUNK; c++) M = fmaxf(M, g_pm[row * NCHUNK + c]);
    float S = 0.f;
#pragma unroll
    for (int c = 0; c < NCHUNK; c++)
        S += g_ps[row * NCHUNK + c] * expf(g_pm[row * NCHUNK + c] - M);
    float lse = M + logf(S);

    float v[7]; int id[7];
#pragma unroll
    for (int j = 0; j < 7; j++) { v[j] = -FLT_MAX; id[j] = 0x7fffffff; }
#pragma unroll
    for (int c = 0; c < NCHUNK; c++) {
#pragma unroll
        for (int q = 0; q < 7; q++) {
            float cv = g_ptv[(row * NCHUNK + c) * 7 + q];
            int   ci = g_pti[(row * NCHUNK + c) * 7 + q];
            if (better(cv, ci, v[6], id[6])) {
                v[6] = cv; id[6] = ci;
#pragma unroll
                for (int j = 6; j > 0; j--) {
                    if (better(v[j], id[j], v[j - 1], id[j - 1])) {
                        float tv = v[j]; v[j] = v[j - 1]; v[j - 1] = tv;
                        int ti = id[j]; id[j] = id[j - 1]; id[j - 1] = ti;
                    }
                }
            }
        }
    }

    int t = targets[row];               // raw target used as oh column (ref quirk)
    float xt = g_x[(size_t)row * XP + t];

    float mx = v[1];
    float es[6], ss = 0.f;
#pragma unroll
    for (int j = 1; j < 7; j++) { es[j - 1] = expf(v[j] - mx); ss += es[j - 1]; }
    float inv = 1.0f / ss;

    float loss = lse - xt;
    float* oh = oh_base + (size_t)row * NX;
#pragma unroll
    for (int j = 1; j < 7; j++) {
        float w = es[j - 1] * inv;
        if (id[j] != t) {
            oh[id[j]] = w;
            loss += w * (lse - v[j]);
        }
    }
    oh[t] = 1.0f;

    __shared__ float sh[256];
    sh[row] = loss; __syncthreads();
    for (int s = 128; s > 0; s >>= 1) {
        if (row < s) sh[row] += sh[row + s];
        __syncthreads();
    }
    if (row == 0) out[0] = sh[0] * (1.0f / 256.0f);
}

// ---------------- launch ----------------
extern "C" void kernel_launch(void* const* d_in, const int* in_sizes, int n_in,
                              void* d_out, int out_size) {
    (void)in_sizes; (void)n_in; (void)out_size;
    const float* inf_  = (const float*)d_in[0];
    const float* ine_  = (const float*)d_in[1];
    const float* prob  = (const float*)d_in[2];
    const float* probe = (const float*)d_in[3];
    const float* queue = (const float*)d_in[4];
    const float* q2in  = (const float*)d_in[5];
    const float* q3in  = (const float*)d_in[6];
    const float* q4in  = (const float*)d_in[7];
    const int*   tgt   = (const int*)d_in[8];
    float* out = (float*)d_out;

    const size_t SZ_Q  = (size_t)F_ * C_;
    const size_t SZ_Q3 = (size_t)P_ * C_;
    float* oq  = out + 1;
    float* oq2 = oq  + SZ_Q;
    float* oq3 = oq2 + SZ_Q;
    float* oq4 = oq3 + SZ_Q3;
    float* ooh = oq4 + SZ_Q3;

    cudaStream_t s1 = 0;
    cudaEvent_t evA = 0, evB = 0, evC = 0;
    bool fork = true;
    if (cudaStreamCreateWithFlags(&s1, cudaStreamNonBlocking) != cudaSuccess) fork = false;
    if (fork && cudaEventCreateWithFlags(&evA, cudaEventDisableTiming) != cudaSuccess) fork = false;
    if (fork && cudaEventCreateWithFlags(&evB, cudaEventDisableTiming) != cudaSuccess) fork = false;
    if (fork && cudaEventCreateWithFlags(&evC, cudaEventDisableTiming) != cudaSuccess) fork = false;

    if (fork) {
        cudaEventRecord(evA, 0);
        cudaStreamWaitEvent(s1, evA, 0);

        // s1: bulk queue copies (pre-update values)
        cudaMemcpyAsync(oq,  queue, SZ_Q  * sizeof(float), cudaMemcpyDeviceToDevice, s1);
        cudaMemcpyAsync(oq2, q2in,  SZ_Q  * sizeof(float), cudaMemcpyDeviceToDevice, s1);
        cudaMemcpyAsync(oq3, q3in,  SZ_Q3 * sizeof(float), cudaMemcpyDeviceToDevice, s1);
        cudaMemcpyAsync(oq4, q4in,  SZ_Q3 * sizeof(float), cudaMemcpyDeviceToDevice, s1);

        // s0: normalize f/ema, split A, then tensor GEMM (B split fused in)
        k_norm_fe<<<B_, 256>>>(inf_, ine_);
        cudaEventRecord(evB, 0);             // g_fn/g_en ready -> s1 may scatter
        k_split_a<<<(B_ * KP) / 256, 256>>>();
        {
            dim3 grid(B_ / GBM, C_ / GBN);   // (4, 256)
            k_gemm_bf16<<<grid, 256>>>(queue);
        }

        // s1: prob normalize, scatter, zero oh
        k_norm_p<<<2 * B_, 256, 0, s1>>>(prob, probe);
        cudaStreamWaitEvent(s1, evB, 0);
        {
            int total = 2 * F_ * B_ + 2 * P_ * B_;
            k_scatter<<<(total + 255) / 256, 256, 0, s1>>>(oq, oq2, oq3, oq4, tgt);
        }
        cudaMemsetAsync(ooh, 0, (size_t)B_ * NX * sizeof(float), s1);
        cudaEventRecord(evC, s1);

        // s0: row stats then finalize
        k_partial<<<B_ * NCHUNK, 256>>>();
        cudaStreamWaitEvent(0, evC, 0);
        k_merge_finalize<<<1, 256>>>(tgt, out, ooh);

        cudaStreamCaptureStatus st = cudaStreamCaptureStatusNone;
        cudaError_t qe = cudaStreamIsCapturing(s1, &st);
        if (qe == cudaSuccess && st == cudaStreamCaptureStatusNone) {
            cudaEventDestroy(evA);
            cudaEventDestroy(evB);
            cudaEventDestroy(evC);
            cudaStreamDestroy(s1);
        }
    } else {
        // -------- sequential fallback --------
        k_norm_fe<<<B_, 256>>>(inf_, ine_);
        k_norm_p<<<2 * B_, 256>>>(prob, probe);
        k_split_a<<<(B_ * KP) / 256, 256>>>();
        {
            dim3 grid(B_ / GBM, C_ / GBN);
            k_gemm_bf16<<<grid, 256>>>(queue);
        }
        cudaMemcpyAsync(oq,  queue, SZ_Q  * sizeof(float), cudaMemcpyDeviceToDevice, 0);
        cudaMemcpyAsync(oq2, q2in,  SZ_Q  * sizeof(float), cudaMemcpyDeviceToDevice, 0);
        cudaMemcpyAsync(oq3, q3in,  SZ_Q3 * sizeof(float), cudaMemcpyDeviceToDevice, 0);
        cudaMemcpyAsync(oq4, q4in,  SZ_Q3 * sizeof(float), cudaMemcpyDeviceToDevice, 0);
        {
            int total = 2 * F_ * B_ + 2 * P_ * B_;
            k_scatter<<<(total + 255) / 256, 256>>>(oq, oq2, oq3, oq4, tgt);
        }
        cudaMemsetAsync(ooh, 0, (size_t)B_ * NX * sizeof(float), 0);
        k_partial<<<B_ * NCHUNK, 256>>>();
        k_merge_finalize<<<1, 256>>>(tgt, out, ooh);
    }
}